// round 12
// baseline (speedup 1.0000x reference)
#include <cuda_runtime.h>
#include <cuda_fp16.h>
#include <math.h>
#include <stdint.h>

// ---------------------------------------------------------------------------
// GPT-2 small forward:  B=2, S=1024, L=4, H=12, E=768, D=64, V=50257
// GEMMs via mma.sync.m16n8k16.f16 with fp16 split operands:
//   layer GEMMs: 3-term (Ah@Bh + Ah@Bl + Al@Bh), err ~2^-22
//   LM head:     2-term (Ah@B + Al@B), B single fp16 (err ~2e-4, verified R10)
// Multi-stage cp.async pipeline (3-4 deep) to cover load latency.
// ---------------------------------------------------------------------------
#define BB 2
#define SS 1024
#define LL 4
#define HH 12
#define EE 768
#define VV 50257
#define DD 64
#define MM (BB*SS)
#define NPADLM 50432        // VV padded to multiple of 256

// Scratch (device globals: allocation-free rule)
__device__ float g_X  [MM * EE];
__device__ float g_QKV[MM * 3 * EE];
__device__ __align__(256) __half g_Ah[MM * EE];
__device__ __align__(256) __half g_Al[MM * EE];
__device__ __align__(256) __half g_Fh[MM * 4 * EE];
__device__ __align__(256) __half g_Fl[MM * 4 * EE];
__device__ __align__(256) __half g_Wh[4 * EE * EE];
__device__ __align__(256) __half g_Wl[4 * EE * EE];
__device__ __align__(256) __half g_LMW[(size_t)NPADLM * EE];

// ---------------------------------------------------------------------------
__device__ __forceinline__ uint32_t smem_u32(const void* p) {
    return (uint32_t)__cvta_generic_to_shared(p);
}
__device__ __forceinline__ void cp16(uint32_t dst, const void* src) {
    asm volatile("cp.async.cg.shared.global [%0], [%1], 16;" :: "r"(dst), "l"(src));
}
__device__ __forceinline__ void mma_f16(float* c, const uint32_t* a, const uint32_t* b) {
    asm volatile(
        "mma.sync.aligned.m16n8k16.row.col.f32.f16.f16.f32 "
        "{%0,%1,%2,%3},{%4,%5,%6,%7},{%8,%9},{%0,%1,%2,%3};"
        : "+f"(c[0]), "+f"(c[1]), "+f"(c[2]), "+f"(c[3])
        : "r"(a[0]), "r"(a[1]), "r"(a[2]), "r"(a[3]), "r"(b[0]), "r"(b[1]));
}
__device__ __forceinline__ void ldmx4(uint32_t* r, uint32_t addr) {
    asm volatile("ldmatrix.sync.aligned.m8n8.x4.shared.b16 {%0,%1,%2,%3}, [%4];"
                 : "=r"(r[0]), "=r"(r[1]), "=r"(r[2]), "=r"(r[3]) : "r"(addr));
}
__device__ __forceinline__ void split_h(float v, __half& hi, __half& lo) {
    hi = __float2half(v);
    lo = __float2half(v - __half2float(hi));
}

// ---------------------------------------------------------------------------
// Embedding
// ---------------------------------------------------------------------------
__global__ void embed_k(const int* __restrict__ tok,
                        const float* __restrict__ wte,
                        const float* __restrict__ wpe,
                        float* __restrict__ X)
{
    int row = blockIdx.x;
    int s   = row & (SS - 1);
    int t   = tok[row];
    const float* we = wte + (size_t)t * EE;
    const float* wp = wpe + (size_t)s * EE;
    float* xr = X + (size_t)row * EE;
    for (int e = threadIdx.x; e < EE; e += blockDim.x)
        xr[e] = we[e] + wp[e];
}

// ---------------------------------------------------------------------------
// LayerNorm -> split fp16 hi/lo
// ---------------------------------------------------------------------------
__global__ __launch_bounds__(256) void ln_split_k(const float* __restrict__ X,
                                                  const float* __restrict__ gam,
                                                  const float* __restrict__ bet,
                                                  __half* __restrict__ Oh,
                                                  __half* __restrict__ Ol)
{
    __shared__ float s1[8], s2[8];
    int row = blockIdx.x, tid = threadIdx.x;
    const float* xr = X + (size_t)row * EE;
    float v[3];
    float sum = 0.f, sq = 0.f;
#pragma unroll
    for (int k = 0; k < 3; k++) {
        v[k] = xr[tid + k * 256];
        sum += v[k];
        sq  += v[k] * v[k];
    }
#pragma unroll
    for (int o = 16; o > 0; o >>= 1) {
        sum += __shfl_xor_sync(0xffffffffu, sum, o);
        sq  += __shfl_xor_sync(0xffffffffu, sq,  o);
    }
    if ((tid & 31) == 0) { s1[tid >> 5] = sum; s2[tid >> 5] = sq; }
    __syncthreads();
    sum = 0.f; sq = 0.f;
#pragma unroll
    for (int i = 0; i < 8; i++) { sum += s1[i]; sq += s2[i]; }
    const float inv_n = 1.0f / (float)EE;
    float mu  = sum * inv_n;
    float var = sq * inv_n - mu * mu;
    float rs  = rsqrtf(var + 1e-5f);
#pragma unroll
    for (int k = 0; k < 3; k++) {
        int e = tid + k * 256;
        float y = (v[k] - mu) * rs * gam[e] + bet[e];
        __half hi, lo; split_h(y, hi, lo);
        Oh[(size_t)row * EE + e] = hi;
        Ol[(size_t)row * EE + e] = lo;
    }
}

// ---------------------------------------------------------------------------
// Weight split+transpose: Bg[K,N] fp32 -> Bh,Bl [N,K] fp16 (3-term weights)
// ---------------------------------------------------------------------------
__global__ void splitT3_k(const float* __restrict__ Bg,
                          __half* __restrict__ Bh,
                          __half* __restrict__ Bl, int K, int N)
{
    __shared__ float t[32][33];
    int n0 = blockIdx.x * 32, k0 = blockIdx.y * 32;
    int tx = threadIdx.x, ty = threadIdx.y;
#pragma unroll
    for (int i = 0; i < 4; i++)
        t[ty + 8 * i][tx] = Bg[(size_t)(k0 + ty + 8 * i) * N + n0 + tx];
    __syncthreads();
#pragma unroll
    for (int i = 0; i < 4; i++) {
        int n = n0 + ty + 8 * i;
        int k = k0 + tx;
        __half hi, lo; split_h(t[tx][ty + 8 * i], hi, lo);
        Bh[(size_t)n * K + k] = hi;
        Bl[(size_t)n * K + k] = lo;
    }
}

// Single-fp16 transpose with zero pad (LM head weights)
__global__ void splitT1_k(const float* __restrict__ Bg,
                          __half* __restrict__ Bo, int K, int N)
{
    __shared__ float t[32][33];
    int n0 = blockIdx.x * 32, k0 = blockIdx.y * 32;
    int tx = threadIdx.x, ty = threadIdx.y;
#pragma unroll
    for (int i = 0; i < 4; i++) {
        int n = n0 + tx;
        t[ty + 8 * i][tx] = (n < N) ? Bg[(size_t)(k0 + ty + 8 * i) * N + n] : 0.f;
    }
    __syncthreads();
#pragma unroll
    for (int i = 0; i < 4; i++) {
        int n = n0 + ty + 8 * i;
        Bo[(size_t)n * K + k0 + tx] = __float2half(t[tx][ty + 8 * i]);
    }
}

// ---------------------------------------------------------------------------
// fp16-split GEMM: C[M,N] = A[M,K] @ W[N,K]^T
// NA/NB: split terms per operand. NA=2,NB=2 -> 3 MMAs (hh+hl+lh);
// NA=2,NB=1 -> 2 MMAs; NSTG-stage cp.async pipeline; RS=40 pad.
// ---------------------------------------------------------------------------
#define RS 40
#define KC 32

template<int BM, int BN, int WM, int WN, int NA, int NB, int NSTG,
         bool BIAS, bool GELU, bool RES, bool NGUARD, bool OSPLIT>
__global__ void __launch_bounds__(((BM/WM)*(BN/WN))*32)
hgemm(const __half* __restrict__ Ah, const __half* __restrict__ Al,
      const __half* __restrict__ Bh, const __half* __restrict__ Bl,
      const float* __restrict__ bias, const float* __restrict__ res,
      float* __restrict__ C, __half* __restrict__ Oh, __half* __restrict__ Ol,
      int N, int K)
{
    constexpr int WARPS_M = BM / WM;
    constexpr int NTHR = WARPS_M * (BN / WN) * 32;
    constexpr int MT = WM / 16, NT = WN / 8;
    constexpr int STG = (NA * BM + NB * BN) * RS;       // halfs per stage
    constexpr int OAl = BM * RS;                        // (only if NA==2)
    constexpr int OBh = NA * BM * RS;
    constexpr int OBl = NA * BM * RS + BN * RS;
    constexpr int CH  = (NA * BM + NB * BN) * 4;        // 16B chunks per stage

    extern __shared__ __half sm[];

    const int tid = threadIdx.x, lane = tid & 31, wid = tid >> 5;
    const int wm = (wid % WARPS_M) * WM, wn = (wid / WARPS_M) * WN;
    const int bm = blockIdx.x * BM, bn = blockIdx.y * BN;

    float acc[MT][NT][4];
#pragma unroll
    for (int i = 0; i < MT; i++)
#pragma unroll
        for (int j = 0; j < NT; j++)
#pragma unroll
            for (int t = 0; t < 4; t++) acc[i][j][t] = 0.f;

    const int nIter = K / KC;

    auto load_stage = [&](int it, int s) {
        const int k0 = it * KC;
#pragma unroll
        for (int t = 0; t < CH / NTHR; t++) {
            int c = tid + t * NTHR;
            int ridx = c >> 2, part = c & 3;
            const __half* g; int off;
            if (NA == 2 && ridx < BM)      { g = Ah + (size_t)(bm + ridx) * K; off = ridx * RS; }
            else if (NA == 2 && ridx < 2 * BM)
                { int r = ridx - BM; g = Al + (size_t)(bm + r) * K; off = OAl + r * RS; }
            else if (NA == 1 && ridx < BM) { g = Ah + (size_t)(bm + ridx) * K; off = ridx * RS; }
            else if (NB == 1 || ridx < NA * BM + BN)
                { int r = ridx - NA * BM; g = Bh + (size_t)(bn + r) * K; off = OBh + r * RS; }
            else
                { int r = ridx - NA * BM - BN; g = Bl + (size_t)(bn + r) * K; off = OBl + r * RS; }
            cp16(smem_u32(sm + s * STG + off + part * 8), g + k0 + part * 8);
        }
        asm volatile("cp.async.commit_group;");
    };

    // Prologue: fill NSTG-1 stages
#pragma unroll
    for (int c = 0; c < NSTG - 1; c++) load_stage(c, c);

    const int a_lane = (wm + (lane & 15)) * RS + ((lane >> 4) << 3);
    const int b_lane = (wn + ((lane >> 4) << 3) + (lane & 7)) * RS + (((lane >> 3) & 1) << 3);

    for (int it = 0; it < nIter; it++) {
        const int s = it % NSTG;
        asm volatile("cp.async.wait_group %0;" :: "n"(NSTG - 2));
        __syncthreads();
        if (it + NSTG - 1 < nIter)
            load_stage(it + NSTG - 1, (it + NSTG - 1) % NSTG);

        const __half* stg = sm + s * STG;
#pragma unroll
        for (int kh = 0; kh < 2; kh++) {
            uint32_t ah[MT][4], al[MT][4];
#pragma unroll
            for (int mt = 0; mt < MT; mt++) {
                ldmx4(ah[mt], smem_u32(stg + a_lane + mt * 16 * RS + kh * 16));
                if (NA == 2)
                    ldmx4(al[mt], smem_u32(stg + OAl + a_lane + mt * 16 * RS + kh * 16));
            }
#pragma unroll
            for (int ntb = 0; ntb < NT / 4; ntb++) {
                uint32_t bh[4][2], bl[4][2];
#pragma unroll
                for (int p = 0; p < 2; p++) {
                    const int nt = ntb * 4 + p * 2;
                    uint32_t r4[4];
                    ldmx4(r4, smem_u32(stg + OBh + b_lane + nt * 8 * RS + kh * 16));
                    bh[p*2][0] = r4[0]; bh[p*2][1] = r4[1];
                    bh[p*2+1][0] = r4[2]; bh[p*2+1][1] = r4[3];
                    if (NB == 2) {
                        ldmx4(r4, smem_u32(stg + OBl + b_lane + nt * 8 * RS + kh * 16));
                        bl[p*2][0] = r4[0]; bl[p*2][1] = r4[1];
                        bl[p*2+1][0] = r4[2]; bl[p*2+1][1] = r4[3];
                    }
                }
#pragma unroll
                for (int mt = 0; mt < MT; mt++)
#pragma unroll
                    for (int j = 0; j < 4; j++) {
                        const int nt = ntb * 4 + j;
                        mma_f16(acc[mt][nt], ah[mt], bh[j]);
                        if (NB == 2) mma_f16(acc[mt][nt], ah[mt], bl[j]);
                        if (NA == 2) mma_f16(acc[mt][nt], al[mt], bh[j]);
                    }
            }
        }
        __syncthreads();
    }

    // Epilogue: per mma tile, (r = fr[+8], c = 2*fc[+1])
    const int fr = lane >> 2, fc = lane & 3;
#pragma unroll
    for (int mt = 0; mt < MT; mt++) {
        int row0 = bm + wm + mt * 16 + fr;
#pragma unroll
        for (int nt = 0; nt < NT; nt++) {
            int col = bn + wn + nt * 8 + 2 * fc;
#pragma unroll
            for (int h = 0; h < 2; h++) {
                int rr = row0 + h * 8;
                float v0 = acc[mt][nt][h * 2 + 0];
                float v1 = acc[mt][nt][h * 2 + 1];
                if (BIAS) { v0 += bias[col]; v1 += bias[col + 1]; }
                if (GELU) {
                    v0 = 0.5f * v0 * (1.f + erff(v0 * 0.70710678118654752f));
                    v1 = 0.5f * v1 * (1.f + erff(v1 * 0.70710678118654752f));
                }
                if (RES) {
                    v0 += res[(size_t)rr * N + col];
                    v1 += res[(size_t)rr * N + col + 1];
                }
                if (OSPLIT) {
                    __half h0, l0, h1, l1;
                    split_h(v0, h0, l0);
                    split_h(v1, h1, l1);
                    *(__half2*)(Oh + (size_t)rr * N + col) = __halves2half2(h0, h1);
                    *(__half2*)(Ol + (size_t)rr * N + col) = __halves2half2(l0, l1);
                } else if (!NGUARD) {
                    *(float2*)&C[(size_t)rr * N + col] = make_float2(v0, v1);
                } else {
                    if (col < N)     C[(size_t)rr * N + col]     = v0;
                    if (col + 1 < N) C[(size_t)rr * N + col + 1] = v1;
                }
            }
        }
    }
}

// ---------------------------------------------------------------------------
// Causal attention (online softmax); epilogue writes split fp16 hi/lo.
// ---------------------------------------------------------------------------
__global__ __launch_bounds__(256) void attn_k(const float* __restrict__ QKV,
                                              __half* __restrict__ Oh,
                                              __half* __restrict__ Ol)
{
    const int TQ = 64, TK = 32;
    __shared__ float Qs[TQ][DD + 1];
    __shared__ float Kt[DD][TK];
    __shared__ float Vs[TK][DD];
    __shared__ float Ps[TQ][TK + 1];
    __shared__ float red[TQ][4];

    int tid = threadIdx.x;
    int qt = blockIdx.x, h = blockIdx.y, b = blockIdx.z;
    int r  = tid >> 2;
    int q4 = tid & 3;
    int qi = qt * TQ + r;

    const size_t rstride = 3 * EE;
    const float* qkvb = QKV + (size_t)b * SS * rstride;

    for (int i = tid; i < TQ * DD; i += 256) {
        int rr = i >> 6, d = i & 63;
        Qs[rr][d] = qkvb[(size_t)(qt * TQ + rr) * rstride + h * DD + d];
    }

    float m = -INFINITY, l = 0.f;
    float o[16];
#pragma unroll
    for (int j = 0; j < 16; j++) o[j] = 0.f;
    const float scale = 0.125f;

    int nkt = (qt + 1) * (TQ / TK);
    for (int kt = 0; kt < nkt; kt++) {
        __syncthreads();
        for (int i = tid; i < TK * DD; i += 256) {
            int rr = i >> 6, d = i & 63;
            size_t base = (size_t)(kt * TK + rr) * rstride + h * DD + d;
            Kt[d][rr] = qkvb[EE + base];
            Vs[rr][d] = qkvb[2 * EE + base];
        }
        __syncthreads();

        float sc[8];
#pragma unroll
        for (int j = 0; j < 8; j++) sc[j] = 0.f;
#pragma unroll 8
        for (int d = 0; d < DD; d++) {
            float qv = Qs[r][d];
            float4 k0 = *(const float4*)&Kt[d][q4 * 8];
            float4 k1 = *(const float4*)&Kt[d][q4 * 8 + 4];
            sc[0] = fmaf(qv, k0.x, sc[0]);
            sc[1] = fmaf(qv, k0.y, sc[1]);
            sc[2] = fmaf(qv, k0.z, sc[2]);
            sc[3] = fmaf(qv, k0.w, sc[3]);
            sc[4] = fmaf(qv, k1.x, sc[4]);
            sc[5] = fmaf(qv, k1.y, sc[5]);
            sc[6] = fmaf(qv, k1.z, sc[6]);
            sc[7] = fmaf(qv, k1.w, sc[7]);
        }
        float lmax = -INFINITY;
#pragma unroll
        for (int j = 0; j < 8; j++) {
            int kg = kt * TK + q4 * 8 + j;
            sc[j] = (kg <= qi) ? sc[j] * scale : -1e30f;
            lmax = fmaxf(lmax, sc[j]);
        }
        red[r][q4] = lmax;
        __syncthreads();
        float mnew = fmaxf(fmaxf(fmaxf(red[r][0], red[r][1]),
                                 fmaxf(red[r][2], red[r][3])), m);
        __syncthreads();

        float lsum = 0.f;
#pragma unroll
        for (int j = 0; j < 8; j++) {
            float p = __expf(sc[j] - mnew);
            Ps[r][q4 * 8 + j] = p;
            lsum += p;
        }
        red[r][q4] = lsum;
        __syncthreads();
        float tsum = red[r][0] + red[r][1] + red[r][2] + red[r][3];
        float fac = __expf(m - mnew);
        l = l * fac + tsum;
        m = mnew;
#pragma unroll
        for (int j = 0; j < 16; j++) o[j] *= fac;

#pragma unroll 4
        for (int c = 0; c < TK; c++) {
            float p = Ps[r][c];
            float4 v0 = *(const float4*)&Vs[c][q4 * 16 + 0];
            float4 v1 = *(const float4*)&Vs[c][q4 * 16 + 4];
            float4 v2 = *(const float4*)&Vs[c][q4 * 16 + 8];
            float4 v3 = *(const float4*)&Vs[c][q4 * 16 + 12];
            o[0]  = fmaf(p, v0.x, o[0]);  o[1]  = fmaf(p, v0.y, o[1]);
            o[2]  = fmaf(p, v0.z, o[2]);  o[3]  = fmaf(p, v0.w, o[3]);
            o[4]  = fmaf(p, v1.x, o[4]);  o[5]  = fmaf(p, v1.y, o[5]);
            o[6]  = fmaf(p, v1.z, o[6]);  o[7]  = fmaf(p, v1.w, o[7]);
            o[8]  = fmaf(p, v2.x, o[8]);  o[9]  = fmaf(p, v2.y, o[9]);
            o[10] = fmaf(p, v2.z, o[10]); o[11] = fmaf(p, v2.w, o[11]);
            o[12] = fmaf(p, v3.x, o[12]); o[13] = fmaf(p, v3.y, o[13]);
            o[14] = fmaf(p, v3.z, o[14]); o[15] = fmaf(p, v3.w, o[15]);
        }
    }

    float inv = 1.f / l;
    size_t obase = ((size_t)b * SS + qi) * EE + h * DD + q4 * 16;
#pragma unroll
    for (int j = 0; j < 16; j++) {
        __half hi, lo;
        split_h(o[j] * inv, hi, lo);
        Oh[obase + j] = hi;
        Ol[obase + j] = lo;
    }
}

// ---------------------------------------------------------------------------
// Host launcher
// ---------------------------------------------------------------------------
extern "C" void kernel_launch(void* const* d_in, const int* in_sizes, int n_in,
                              void* d_out, int out_size)
{
    const int*   tok    = (const int*)  d_in[0];
    const float* wte    = (const float*)d_in[1];
    const float* wpe    = (const float*)d_in[2];
    const float* ln1_g  = (const float*)d_in[3];
    const float* ln1_b  = (const float*)d_in[4];
    const float* attn_w = (const float*)d_in[5];
    const float* attn_b = (const float*)d_in[6];
    const float* proj_w = (const float*)d_in[7];
    const float* proj_b = (const float*)d_in[8];
    const float* ln2_g  = (const float*)d_in[9];
    const float* ln2_b  = (const float*)d_in[10];
    const float* fc_w   = (const float*)d_in[11];
    const float* fc_b   = (const float*)d_in[12];
    const float* fc2_w  = (const float*)d_in[13];
    const float* fc2_b  = (const float*)d_in[14];
    const float* lnf_g  = (const float*)d_in[15];
    const float* lnf_b  = (const float*)d_in[16];
    const float* lm_w   = (const float*)d_in[17];
    float* out = (float*)d_out;

    float *X, *QKV;
    __half *Ah, *Al, *Fh, *Fl, *Wh, *Wl, *LMW;
    cudaGetSymbolAddress((void**)&X,   g_X);
    cudaGetSymbolAddress((void**)&QKV, g_QKV);
    cudaGetSymbolAddress((void**)&Ah,  g_Ah);
    cudaGetSymbolAddress((void**)&Al,  g_Al);
    cudaGetSymbolAddress((void**)&Fh,  g_Fh);
    cudaGetSymbolAddress((void**)&Fl,  g_Fl);
    cudaGetSymbolAddress((void**)&Wh,  g_Wh);
    cudaGetSymbolAddress((void**)&Wl,  g_Wl);
    cudaGetSymbolAddress((void**)&LMW, g_LMW);

    // GEMM configs
    //  qkv/fc1: 128x256 tile, 3-term, 3-stage pipeline
    //  proj/fc2: 64x128 tile, 3-term, 4-stage pipeline
    //  LM head: 128x256 tile, 2-term (A split, B fp16), 4-stage pipeline
    auto qkv_f = hgemm<128,256,64,64,2,2,3, true,false,false,false,false>;
    auto fc1_f = hgemm<128,256,64,64,2,2,3, true,true, false,false,true>;
    auto sml_f = hgemm< 64,128,32,64,2,2,4, true,false,true, false,false>;
    auto lm_f  = hgemm<128,256,64,64,2,1,4, false,false,false,true,false>;

    const int SM_BIG3 = 3 * (2*128 + 2*256) * RS * 2;   // 184320 B
    const int SM_SML3 = 4 * (2*64  + 2*128) * RS * 2;   // 122880 B
    const int SM_LM   = 4 * (2*128 + 1*256) * RS * 2;   // 163840 B
    cudaFuncSetAttribute(qkv_f, cudaFuncAttributeMaxDynamicSharedMemorySize, SM_BIG3);
    cudaFuncSetAttribute(fc1_f, cudaFuncAttributeMaxDynamicSharedMemorySize, SM_BIG3);
    cudaFuncSetAttribute(sml_f, cudaFuncAttributeMaxDynamicSharedMemorySize, SM_SML3);
    cudaFuncSetAttribute(lm_f,  cudaFuncAttributeMaxDynamicSharedMemorySize, SM_LM);

    embed_k<<<MM, 256>>>(tok, wte, wpe, X);

    for (int i = 0; i < LL; i++) {
        // LN1 -> split
        ln_split_k<<<MM, 256>>>(X, ln1_g + i * EE, ln1_b + i * EE, Ah, Al);
        // QKV = A @ attn_w + b    [2048 x 2304]
        splitT3_k<<<dim3(3 * EE / 32, EE / 32), dim3(32, 8)>>>(
            attn_w + (size_t)i * EE * 3 * EE, Wh, Wl, EE, 3 * EE);
        qkv_f<<<dim3(MM / 128, 3 * EE / 256), 256, SM_BIG3>>>(
            Ah, Al, Wh, Wl, attn_b + (size_t)i * 3 * EE, nullptr,
            QKV, nullptr, nullptr, 3 * EE, EE);
        // attention -> split
        attn_k<<<dim3(SS / 64, HH, BB), 256>>>(QKV, Ah, Al);
        // X += A @ proj_w + b     [2048 x 768]
        splitT3_k<<<dim3(EE / 32, EE / 32), dim3(32, 8)>>>(
            proj_w + (size_t)i * EE * EE, Wh, Wl, EE, EE);
        sml_f<<<dim3(MM / 64, EE / 128), 128, SM_SML3>>>(
            Ah, Al, Wh, Wl, proj_b + (size_t)i * EE, X,
            X, nullptr, nullptr, EE, EE);
        // LN2 -> split
        ln_split_k<<<MM, 256>>>(X, ln2_g + i * EE, ln2_b + i * EE, Ah, Al);
        // F = gelu(A @ fc_w + b) -> split   [2048 x 3072]
        splitT3_k<<<dim3(4 * EE / 32, EE / 32), dim3(32, 8)>>>(
            fc_w + (size_t)i * EE * 4 * EE, Wh, Wl, EE, 4 * EE);
        fc1_f<<<dim3(MM / 128, 4 * EE / 256), 256, SM_BIG3>>>(
            Ah, Al, Wh, Wl, fc_b + (size_t)i * 4 * EE, nullptr,
            nullptr, Fh, Fl, 4 * EE, EE);
        // X += F @ fc2_w + b      [2048 x 768], K=3072
        splitT3_k<<<dim3(EE / 32, 4 * EE / 32), dim3(32, 8)>>>(
            fc2_w + (size_t)i * 4 * EE * EE, Wh, Wl, 4 * EE, EE);
        sml_f<<<dim3(MM / 64, EE / 128), 128, SM_SML3>>>(
            Fh, Fl, Wh, Wl, fc2_b + (size_t)i * EE, X,
            X, nullptr, nullptr, EE, 4 * EE);
    }

    // final LN -> split, LM head (2-term: A split, B fp16; guarded stores)
    ln_split_k<<<MM, 256>>>(X, lnf_g, lnf_b, Ah, Al);
    splitT1_k<<<dim3(NPADLM / 32, EE / 32), dim3(32, 8)>>>(lm_w, LMW, EE, VV);
    lm_f<<<dim3(MM / 128, NPADLM / 256), 256, SM_LM>>>(
        Ah, Al, LMW, nullptr, nullptr, nullptr,
        out, nullptr, nullptr, VV, EE);
}

// round 13
// speedup vs baseline: 1.0092x; 1.0092x over previous
#include <cuda_runtime.h>
#include <cuda_fp16.h>
#include <math.h>
#include <stdint.h>

// ---------------------------------------------------------------------------
// GPT-2 small forward:  B=2, S=1024, L=4, H=12, E=768, D=64, V=50257
// GEMMs via mma.sync.m16n8k16.f16 with fp16 split operands:
//   layer GEMMs: 3-term (Ah@Bh + Ah@Bl + Al@Bh), err ~2^-22
//   LM head:     2-term (Ah@B + Al@B), B single fp16 (verified R10: 2.08e-4)
// This round: occupancy push — 16 warps/SM on every GEMM.
// ---------------------------------------------------------------------------
#define BB 2
#define SS 1024
#define LL 4
#define HH 12
#define EE 768
#define VV 50257
#define DD 64
#define MM (BB*SS)
#define NPADLM 50432        // VV padded to multiple of 256

// Scratch (device globals: allocation-free rule)
__device__ float g_X  [MM * EE];
__device__ float g_QKV[MM * 3 * EE];
__device__ __align__(256) __half g_Ah[MM * EE];
__device__ __align__(256) __half g_Al[MM * EE];
__device__ __align__(256) __half g_Fh[MM * 4 * EE];
__device__ __align__(256) __half g_Fl[MM * 4 * EE];
__device__ __align__(256) __half g_Wh[4 * EE * EE];
__device__ __align__(256) __half g_Wl[4 * EE * EE];
__device__ __align__(256) __half g_LMW[(size_t)NPADLM * EE];

// ---------------------------------------------------------------------------
__device__ __forceinline__ uint32_t smem_u32(const void* p) {
    return (uint32_t)__cvta_generic_to_shared(p);
}
__device__ __forceinline__ void cp16(uint32_t dst, const void* src) {
    asm volatile("cp.async.cg.shared.global [%0], [%1], 16;" :: "r"(dst), "l"(src));
}
__device__ __forceinline__ void mma_f16(float* c, const uint32_t* a, const uint32_t* b) {
    asm volatile(
        "mma.sync.aligned.m16n8k16.row.col.f32.f16.f16.f32 "
        "{%0,%1,%2,%3},{%4,%5,%6,%7},{%8,%9},{%0,%1,%2,%3};"
        : "+f"(c[0]), "+f"(c[1]), "+f"(c[2]), "+f"(c[3])
        : "r"(a[0]), "r"(a[1]), "r"(a[2]), "r"(a[3]), "r"(b[0]), "r"(b[1]));
}
__device__ __forceinline__ void ldmx4(uint32_t* r, uint32_t addr) {
    asm volatile("ldmatrix.sync.aligned.m8n8.x4.shared.b16 {%0,%1,%2,%3}, [%4];"
                 : "=r"(r[0]), "=r"(r[1]), "=r"(r[2]), "=r"(r[3]) : "r"(addr));
}
__device__ __forceinline__ void split_h(float v, __half& hi, __half& lo) {
    hi = __float2half(v);
    lo = __float2half(v - __half2float(hi));
}

// ---------------------------------------------------------------------------
// Embedding
// ---------------------------------------------------------------------------
__global__ void embed_k(const int* __restrict__ tok,
                        const float* __restrict__ wte,
                        const float* __restrict__ wpe,
                        float* __restrict__ X)
{
    int row = blockIdx.x;
    int s   = row & (SS - 1);
    int t   = tok[row];
    const float* we = wte + (size_t)t * EE;
    const float* wp = wpe + (size_t)s * EE;
    float* xr = X + (size_t)row * EE;
    for (int e = threadIdx.x; e < EE; e += blockDim.x)
        xr[e] = we[e] + wp[e];
}

// ---------------------------------------------------------------------------
// LayerNorm -> split fp16 hi/lo
// ---------------------------------------------------------------------------
__global__ __launch_bounds__(256) void ln_split_k(const float* __restrict__ X,
                                                  const float* __restrict__ gam,
                                                  const float* __restrict__ bet,
                                                  __half* __restrict__ Oh,
                                                  __half* __restrict__ Ol)
{
    __shared__ float s1[8], s2[8];
    int row = blockIdx.x, tid = threadIdx.x;
    const float* xr = X + (size_t)row * EE;
    float v[3];
    float sum = 0.f, sq = 0.f;
#pragma unroll
    for (int k = 0; k < 3; k++) {
        v[k] = xr[tid + k * 256];
        sum += v[k];
        sq  += v[k] * v[k];
    }
#pragma unroll
    for (int o = 16; o > 0; o >>= 1) {
        sum += __shfl_xor_sync(0xffffffffu, sum, o);
        sq  += __shfl_xor_sync(0xffffffffu, sq,  o);
    }
    if ((tid & 31) == 0) { s1[tid >> 5] = sum; s2[tid >> 5] = sq; }
    __syncthreads();
    sum = 0.f; sq = 0.f;
#pragma unroll
    for (int i = 0; i < 8; i++) { sum += s1[i]; sq += s2[i]; }
    const float inv_n = 1.0f / (float)EE;
    float mu  = sum * inv_n;
    float var = sq * inv_n - mu * mu;
    float rs  = rsqrtf(var + 1e-5f);
#pragma unroll
    for (int k = 0; k < 3; k++) {
        int e = tid + k * 256;
        float y = (v[k] - mu) * rs * gam[e] + bet[e];
        __half hi, lo; split_h(y, hi, lo);
        Oh[(size_t)row * EE + e] = hi;
        Ol[(size_t)row * EE + e] = lo;
    }
}

// ---------------------------------------------------------------------------
// Weight split+transpose: Bg[K,N] fp32 -> Bh,Bl [N,K] fp16 (3-term weights)
// ---------------------------------------------------------------------------
__global__ void splitT3_k(const float* __restrict__ Bg,
                          __half* __restrict__ Bh,
                          __half* __restrict__ Bl, int K, int N)
{
    __shared__ float t[32][33];
    int n0 = blockIdx.x * 32, k0 = blockIdx.y * 32;
    int tx = threadIdx.x, ty = threadIdx.y;
#pragma unroll
    for (int i = 0; i < 4; i++)
        t[ty + 8 * i][tx] = Bg[(size_t)(k0 + ty + 8 * i) * N + n0 + tx];
    __syncthreads();
#pragma unroll
    for (int i = 0; i < 4; i++) {
        int n = n0 + ty + 8 * i;
        int k = k0 + tx;
        __half hi, lo; split_h(t[tx][ty + 8 * i], hi, lo);
        Bh[(size_t)n * K + k] = hi;
        Bl[(size_t)n * K + k] = lo;
    }
}

// Single-fp16 transpose with zero pad (LM head weights)
__global__ void splitT1_k(const float* __restrict__ Bg,
                          __half* __restrict__ Bo, int K, int N)
{
    __shared__ float t[32][33];
    int n0 = blockIdx.x * 32, k0 = blockIdx.y * 32;
    int tx = threadIdx.x, ty = threadIdx.y;
#pragma unroll
    for (int i = 0; i < 4; i++) {
        int n = n0 + tx;
        t[ty + 8 * i][tx] = (n < N) ? Bg[(size_t)(k0 + ty + 8 * i) * N + n] : 0.f;
    }
    __syncthreads();
#pragma unroll
    for (int i = 0; i < 4; i++) {
        int n = n0 + ty + 8 * i;
        Bo[(size_t)n * K + k0 + tx] = __float2half(t[tx][ty + 8 * i]);
    }
}

// ---------------------------------------------------------------------------
// fp16-split GEMM: C[M,N] = A[M,K] @ W[N,K]^T
// NA/NB: split terms per operand. NA=2,NB=2 -> 3 MMAs (hh+hl+lh);
// NA=2,NB=1 -> 2 MMAs; NSTG-stage cp.async pipeline; RS=40 pad.
// ---------------------------------------------------------------------------
#define RS 40
#define KC 32

template<int BM, int BN, int WM, int WN, int NA, int NB, int NSTG,
         bool BIAS, bool GELU, bool RES, bool NGUARD, bool OSPLIT>
__global__ void __launch_bounds__(((BM/WM)*(BN/WN))*32)
hgemm(const __half* __restrict__ Ah, const __half* __restrict__ Al,
      const __half* __restrict__ Bh, const __half* __restrict__ Bl,
      const float* __restrict__ bias, const float* __restrict__ res,
      float* __restrict__ C, __half* __restrict__ Oh, __half* __restrict__ Ol,
      int N, int K)
{
    constexpr int WARPS_M = BM / WM;
    constexpr int NTHR = WARPS_M * (BN / WN) * 32;
    constexpr int MT = WM / 16, NT = WN / 8;
    constexpr int STG = (NA * BM + NB * BN) * RS;       // halfs per stage
    constexpr int OAl = BM * RS;                        // (only if NA==2)
    constexpr int OBh = NA * BM * RS;
    constexpr int OBl = NA * BM * RS + BN * RS;
    constexpr int CH  = (NA * BM + NB * BN) * 4;        // 16B chunks per stage

    extern __shared__ __half sm[];

    const int tid = threadIdx.x, lane = tid & 31, wid = tid >> 5;
    const int wm = (wid % WARPS_M) * WM, wn = (wid / WARPS_M) * WN;
    const int bm = blockIdx.x * BM, bn = blockIdx.y * BN;

    float acc[MT][NT][4];
#pragma unroll
    for (int i = 0; i < MT; i++)
#pragma unroll
        for (int j = 0; j < NT; j++)
#pragma unroll
            for (int t = 0; t < 4; t++) acc[i][j][t] = 0.f;

    const int nIter = K / KC;

    auto load_stage = [&](int it, int s) {
        const int k0 = it * KC;
#pragma unroll
        for (int t = 0; t < CH / NTHR; t++) {
            int c = tid + t * NTHR;
            int ridx = c >> 2, part = c & 3;
            const __half* g; int off;
            if (NA == 2 && ridx < BM)      { g = Ah + (size_t)(bm + ridx) * K; off = ridx * RS; }
            else if (NA == 2 && ridx < 2 * BM)
                { int r = ridx - BM; g = Al + (size_t)(bm + r) * K; off = OAl + r * RS; }
            else if (NA == 1 && ridx < BM) { g = Ah + (size_t)(bm + ridx) * K; off = ridx * RS; }
            else if (NB == 1 || ridx < NA * BM + BN)
                { int r = ridx - NA * BM; g = Bh + (size_t)(bn + r) * K; off = OBh + r * RS; }
            else
                { int r = ridx - NA * BM - BN; g = Bl + (size_t)(bn + r) * K; off = OBl + r * RS; }
            cp16(smem_u32(sm + s * STG + off + part * 8), g + k0 + part * 8);
        }
        asm volatile("cp.async.commit_group;");
    };

    // Prologue: fill NSTG-1 stages
#pragma unroll
    for (int c = 0; c < NSTG - 1; c++) load_stage(c, c);

    const int a_lane = (wm + (lane & 15)) * RS + ((lane >> 4) << 3);
    const int b_lane = (wn + ((lane >> 4) << 3) + (lane & 7)) * RS + (((lane >> 3) & 1) << 3);

    for (int it = 0; it < nIter; it++) {
        const int s = it % NSTG;
        asm volatile("cp.async.wait_group %0;" :: "n"(NSTG - 2));
        __syncthreads();
        if (it + NSTG - 1 < nIter)
            load_stage(it + NSTG - 1, (it + NSTG - 1) % NSTG);

        const __half* stg = sm + s * STG;
#pragma unroll
        for (int kh = 0; kh < 2; kh++) {
            uint32_t ah[MT][4], al[MT][4];
#pragma unroll
            for (int mt = 0; mt < MT; mt++) {
                ldmx4(ah[mt], smem_u32(stg + a_lane + mt * 16 * RS + kh * 16));
                if (NA == 2)
                    ldmx4(al[mt], smem_u32(stg + OAl + a_lane + mt * 16 * RS + kh * 16));
            }
#pragma unroll
            for (int ntb = 0; ntb < NT / 4; ntb++) {
                uint32_t bh[4][2], bl[4][2];
#pragma unroll
                for (int p = 0; p < 2; p++) {
                    const int nt = ntb * 4 + p * 2;
                    uint32_t r4[4];
                    ldmx4(r4, smem_u32(stg + OBh + b_lane + nt * 8 * RS + kh * 16));
                    bh[p*2][0] = r4[0]; bh[p*2][1] = r4[1];
                    bh[p*2+1][0] = r4[2]; bh[p*2+1][1] = r4[3];
                    if (NB == 2) {
                        ldmx4(r4, smem_u32(stg + OBl + b_lane + nt * 8 * RS + kh * 16));
                        bl[p*2][0] = r4[0]; bl[p*2][1] = r4[1];
                        bl[p*2+1][0] = r4[2]; bl[p*2+1][1] = r4[3];
                    }
                }
#pragma unroll
                for (int mt = 0; mt < MT; mt++)
#pragma unroll
                    for (int j = 0; j < 4; j++) {
                        const int nt = ntb * 4 + j;
                        mma_f16(acc[mt][nt], ah[mt], bh[j]);
                        if (NB == 2) mma_f16(acc[mt][nt], ah[mt], bl[j]);
                        if (NA == 2) mma_f16(acc[mt][nt], al[mt], bh[j]);
                    }
            }
        }
        __syncthreads();
    }

    // Epilogue: per mma tile, (r = fr[+8], c = 2*fc[+1])
    const int fr = lane >> 2, fc = lane & 3;
#pragma unroll
    for (int mt = 0; mt < MT; mt++) {
        int row0 = bm + wm + mt * 16 + fr;
#pragma unroll
        for (int nt = 0; nt < NT; nt++) {
            int col = bn + wn + nt * 8 + 2 * fc;
#pragma unroll
            for (int h = 0; h < 2; h++) {
                int rr = row0 + h * 8;
                float v0 = acc[mt][nt][h * 2 + 0];
                float v1 = acc[mt][nt][h * 2 + 1];
                if (BIAS) { v0 += bias[col]; v1 += bias[col + 1]; }
                if (GELU) {
                    v0 = 0.5f * v0 * (1.f + erff(v0 * 0.70710678118654752f));
                    v1 = 0.5f * v1 * (1.f + erff(v1 * 0.70710678118654752f));
                }
                if (RES) {
                    v0 += res[(size_t)rr * N + col];
                    v1 += res[(size_t)rr * N + col + 1];
                }
                if (OSPLIT) {
                    __half h0, l0, h1, l1;
                    split_h(v0, h0, l0);
                    split_h(v1, h1, l1);
                    *(__half2*)(Oh + (size_t)rr * N + col) = __halves2half2(h0, h1);
                    *(__half2*)(Ol + (size_t)rr * N + col) = __halves2half2(l0, l1);
                } else if (!NGUARD) {
                    *(float2*)&C[(size_t)rr * N + col] = make_float2(v0, v1);
                } else {
                    if (col < N)     C[(size_t)rr * N + col]     = v0;
                    if (col + 1 < N) C[(size_t)rr * N + col + 1] = v1;
                }
            }
        }
    }
}

// ---------------------------------------------------------------------------
// Causal attention (online softmax); epilogue writes split fp16 hi/lo.
// ---------------------------------------------------------------------------
__global__ __launch_bounds__(256) void attn_k(const float* __restrict__ QKV,
                                              __half* __restrict__ Oh,
                                              __half* __restrict__ Ol)
{
    const int TQ = 64, TK = 32;
    __shared__ float Qs[TQ][DD + 1];
    __shared__ float Kt[DD][TK];
    __shared__ float Vs[TK][DD];
    __shared__ float Ps[TQ][TK + 1];
    __shared__ float red[TQ][4];

    int tid = threadIdx.x;
    int qt = blockIdx.x, h = blockIdx.y, b = blockIdx.z;
    int r  = tid >> 2;
    int q4 = tid & 3;
    int qi = qt * TQ + r;

    const size_t rstride = 3 * EE;
    const float* qkvb = QKV + (size_t)b * SS * rstride;

    for (int i = tid; i < TQ * DD; i += 256) {
        int rr = i >> 6, d = i & 63;
        Qs[rr][d] = qkvb[(size_t)(qt * TQ + rr) * rstride + h * DD + d];
    }

    float m = -INFINITY, l = 0.f;
    float o[16];
#pragma unroll
    for (int j = 0; j < 16; j++) o[j] = 0.f;
    const float scale = 0.125f;

    int nkt = (qt + 1) * (TQ / TK);
    for (int kt = 0; kt < nkt; kt++) {
        __syncthreads();
        for (int i = tid; i < TK * DD; i += 256) {
            int rr = i >> 6, d = i & 63;
            size_t base = (size_t)(kt * TK + rr) * rstride + h * DD + d;
            Kt[d][rr] = qkvb[EE + base];
            Vs[rr][d] = qkvb[2 * EE + base];
        }
        __syncthreads();

        float sc[8];
#pragma unroll
        for (int j = 0; j < 8; j++) sc[j] = 0.f;
#pragma unroll 8
        for (int d = 0; d < DD; d++) {
            float qv = Qs[r][d];
            float4 k0 = *(const float4*)&Kt[d][q4 * 8];
            float4 k1 = *(const float4*)&Kt[d][q4 * 8 + 4];
            sc[0] = fmaf(qv, k0.x, sc[0]);
            sc[1] = fmaf(qv, k0.y, sc[1]);
            sc[2] = fmaf(qv, k0.z, sc[2]);
            sc[3] = fmaf(qv, k0.w, sc[3]);
            sc[4] = fmaf(qv, k1.x, sc[4]);
            sc[5] = fmaf(qv, k1.y, sc[5]);
            sc[6] = fmaf(qv, k1.z, sc[6]);
            sc[7] = fmaf(qv, k1.w, sc[7]);
        }
        float lmax = -INFINITY;
#pragma unroll
        for (int j = 0; j < 8; j++) {
            int kg = kt * TK + q4 * 8 + j;
            sc[j] = (kg <= qi) ? sc[j] * scale : -1e30f;
            lmax = fmaxf(lmax, sc[j]);
        }
        red[r][q4] = lmax;
        __syncthreads();
        float mnew = fmaxf(fmaxf(fmaxf(red[r][0], red[r][1]),
                                 fmaxf(red[r][2], red[r][3])), m);
        __syncthreads();

        float lsum = 0.f;
#pragma unroll
        for (int j = 0; j < 8; j++) {
            float p = __expf(sc[j] - mnew);
            Ps[r][q4 * 8 + j] = p;
            lsum += p;
        }
        red[r][q4] = lsum;
        __syncthreads();
        float tsum = red[r][0] + red[r][1] + red[r][2] + red[r][3];
        float fac = __expf(m - mnew);
        l = l * fac + tsum;
        m = mnew;
#pragma unroll
        for (int j = 0; j < 16; j++) o[j] *= fac;

#pragma unroll 4
        for (int c = 0; c < TK; c++) {
            float p = Ps[r][c];
            float4 v0 = *(const float4*)&Vs[c][q4 * 16 + 0];
            float4 v1 = *(const float4*)&Vs[c][q4 * 16 + 4];
            float4 v2 = *(const float4*)&Vs[c][q4 * 16 + 8];
            float4 v3 = *(const float4*)&Vs[c][q4 * 16 + 12];
            o[0]  = fmaf(p, v0.x, o[0]);  o[1]  = fmaf(p, v0.y, o[1]);
            o[2]  = fmaf(p, v0.z, o[2]);  o[3]  = fmaf(p, v0.w, o[3]);
            o[4]  = fmaf(p, v1.x, o[4]);  o[5]  = fmaf(p, v1.y, o[5]);
            o[6]  = fmaf(p, v1.z, o[6]);  o[7]  = fmaf(p, v1.w, o[7]);
            o[8]  = fmaf(p, v2.x, o[8]);  o[9]  = fmaf(p, v2.y, o[9]);
            o[10] = fmaf(p, v2.z, o[10]); o[11] = fmaf(p, v2.w, o[11]);
            o[12] = fmaf(p, v3.x, o[12]); o[13] = fmaf(p, v3.y, o[13]);
            o[14] = fmaf(p, v3.z, o[14]); o[15] = fmaf(p, v3.w, o[15]);
        }
    }

    float inv = 1.f / l;
    size_t obase = ((size_t)b * SS + qi) * EE + h * DD + q4 * 16;
#pragma unroll
    for (int j = 0; j < 16; j++) {
        __half hi, lo;
        split_h(o[j] * inv, hi, lo);
        Oh[obase + j] = hi;
        Ol[obase + j] = lo;
    }
}

// ---------------------------------------------------------------------------
// Host launcher
// ---------------------------------------------------------------------------
extern "C" void kernel_launch(void* const* d_in, const int* in_sizes, int n_in,
                              void* d_out, int out_size)
{
    const int*   tok    = (const int*)  d_in[0];
    const float* wte    = (const float*)d_in[1];
    const float* wpe    = (const float*)d_in[2];
    const float* ln1_g  = (const float*)d_in[3];
    const float* ln1_b  = (const float*)d_in[4];
    const float* attn_w = (const float*)d_in[5];
    const float* attn_b = (const float*)d_in[6];
    const float* proj_w = (const float*)d_in[7];
    const float* proj_b = (const float*)d_in[8];
    const float* ln2_g  = (const float*)d_in[9];
    const float* ln2_b  = (const float*)d_in[10];
    const float* fc_w   = (const float*)d_in[11];
    const float* fc_b   = (const float*)d_in[12];
    const float* fc2_w  = (const float*)d_in[13];
    const float* fc2_b  = (const float*)d_in[14];
    const float* lnf_g  = (const float*)d_in[15];
    const float* lnf_b  = (const float*)d_in[16];
    const float* lm_w   = (const float*)d_in[17];
    float* out = (float*)d_out;

    float *X, *QKV;
    __half *Ah, *Al, *Fh, *Fl, *Wh, *Wl, *LMW;
    cudaGetSymbolAddress((void**)&X,   g_X);
    cudaGetSymbolAddress((void**)&QKV, g_QKV);
    cudaGetSymbolAddress((void**)&Ah,  g_Ah);
    cudaGetSymbolAddress((void**)&Al,  g_Al);
    cudaGetSymbolAddress((void**)&Fh,  g_Fh);
    cudaGetSymbolAddress((void**)&Fl,  g_Fl);
    cudaGetSymbolAddress((void**)&Wh,  g_Wh);
    cudaGetSymbolAddress((void**)&Wl,  g_Wl);
    cudaGetSymbolAddress((void**)&LMW, g_LMW);

    // GEMM configs (occupancy push: 16 warps/SM everywhere)
    //  qkv/fc1: 128x256 tile, 512 thr (16 warps, 32x64 warp tiles), 3-term
    //  proj/fc2: 64x128 tile, 256 thr (8 warps, 32x32), 3-term, 2 CTAs/SM
    //  LM head: 128x256 tile, 512 thr, 2-term (A split, B fp16)
    auto qkv_f = hgemm<128,256,32,64,2,2,2, true,false,false,false,false>;
    auto fc1_f = hgemm<128,256,32,64,2,2,2, true,true, false,false,true>;
    auto sml_f = hgemm< 64,128,32,32,2,2,3, true,false,true, false,false>;
    auto lm_f  = hgemm<128,256,32,64,2,1,2, false,false,false,true,false>;

    const int SM_BIG3 = 2 * (2*128 + 2*256) * RS * 2;   // 122880 B
    const int SM_SML3 = 3 * (2*64  + 2*128) * RS * 2;   //  92160 B
    const int SM_LM   = 2 * (2*128 + 1*256) * RS * 2;   //  81920 B
    cudaFuncSetAttribute(qkv_f, cudaFuncAttributeMaxDynamicSharedMemorySize, SM_BIG3);
    cudaFuncSetAttribute(fc1_f, cudaFuncAttributeMaxDynamicSharedMemorySize, SM_BIG3);
    cudaFuncSetAttribute(sml_f, cudaFuncAttributeMaxDynamicSharedMemorySize, SM_SML3);
    cudaFuncSetAttribute(lm_f,  cudaFuncAttributeMaxDynamicSharedMemorySize, SM_LM);

    embed_k<<<MM, 256>>>(tok, wte, wpe, X);

    for (int i = 0; i < LL; i++) {
        // LN1 -> split
        ln_split_k<<<MM, 256>>>(X, ln1_g + i * EE, ln1_b + i * EE, Ah, Al);
        // QKV = A @ attn_w + b    [2048 x 2304]
        splitT3_k<<<dim3(3 * EE / 32, EE / 32), dim3(32, 8)>>>(
            attn_w + (size_t)i * EE * 3 * EE, Wh, Wl, EE, 3 * EE);
        qkv_f<<<dim3(MM / 128, 3 * EE / 256), 512, SM_BIG3>>>(
            Ah, Al, Wh, Wl, attn_b + (size_t)i * 3 * EE, nullptr,
            QKV, nullptr, nullptr, 3 * EE, EE);
        // attention -> split
        attn_k<<<dim3(SS / 64, HH, BB), 256>>>(QKV, Ah, Al);
        // X += A @ proj_w + b     [2048 x 768]
        splitT3_k<<<dim3(EE / 32, EE / 32), dim3(32, 8)>>>(
            proj_w + (size_t)i * EE * EE, Wh, Wl, EE, EE);
        sml_f<<<dim3(MM / 64, EE / 128), 256, SM_SML3>>>(
            Ah, Al, Wh, Wl, proj_b + (size_t)i * EE, X,
            X, nullptr, nullptr, EE, EE);
        // LN2 -> split
        ln_split_k<<<MM, 256>>>(X, ln2_g + i * EE, ln2_b + i * EE, Ah, Al);
        // F = gelu(A @ fc_w + b) -> split   [2048 x 3072]
        splitT3_k<<<dim3(4 * EE / 32, EE / 32), dim3(32, 8)>>>(
            fc_w + (size_t)i * EE * 4 * EE, Wh, Wl, EE, 4 * EE);
        fc1_f<<<dim3(MM / 128, 4 * EE / 256), 512, SM_BIG3>>>(
            Ah, Al, Wh, Wl, fc_b + (size_t)i * 4 * EE, nullptr,
            nullptr, Fh, Fl, 4 * EE, EE);
        // X += F @ fc2_w + b      [2048 x 768], K=3072
        splitT3_k<<<dim3(EE / 32, 4 * EE / 32), dim3(32, 8)>>>(
            fc2_w + (size_t)i * 4 * EE * EE, Wh, Wl, 4 * EE, EE);
        sml_f<<<dim3(MM / 64, EE / 128), 256, SM_SML3>>>(
            Fh, Fl, Wh, Wl, fc2_b + (size_t)i * EE, X,
            X, nullptr, nullptr, EE, 4 * EE);
    }

    // final LN -> split, LM head (2-term: A split, B fp16; guarded stores)
    ln_split_k<<<MM, 256>>>(X, lnf_g, lnf_b, Ah, Al);
    splitT1_k<<<dim3(NPADLM / 32, EE / 32), dim3(32, 8)>>>(lm_w, LMW, EE, VV);
    lm_f<<<dim3(MM / 128, NPADLM / 256), 512, SM_LM>>>(
        Ah, Al, LMW, nullptr, nullptr, nullptr,
        out, nullptr, nullptr, VV, EE);
}

// round 14
// speedup vs baseline: 1.0241x; 1.0148x over previous
#include <cuda_runtime.h>
#include <cuda_fp16.h>
#include <math.h>
#include <stdint.h>

// ---------------------------------------------------------------------------
// GPT-2 small forward:  B=2, S=1024, L=4, H=12, E=768, D=64, V=50257
// GEMMs via mma.sync.m16n8k16.f16 with fp16 split operands:
//   layer GEMMs: 3-term (Ah@Bh + Ah@Bl + Al@Bh), err ~2^-22
//   LM head:     2-term (Ah@B + Al@B), B single fp16 (verified: 2.08e-4)
// This round: all layer GEMMs on 128x128 tiles @ 512 thr (16 warps/SM).
// ---------------------------------------------------------------------------
#define BB 2
#define SS 1024
#define LL 4
#define HH 12
#define EE 768
#define VV 50257
#define DD 64
#define MM (BB*SS)
#define NPADLM 50432        // VV padded to multiple of 256

// Scratch (device globals: allocation-free rule)
__device__ float g_X  [MM * EE];
__device__ float g_QKV[MM * 3 * EE];
__device__ __align__(256) __half g_Ah[MM * EE];
__device__ __align__(256) __half g_Al[MM * EE];
__device__ __align__(256) __half g_Fh[MM * 4 * EE];
__device__ __align__(256) __half g_Fl[MM * 4 * EE];
__device__ __align__(256) __half g_Wh[4 * EE * EE];
__device__ __align__(256) __half g_Wl[4 * EE * EE];
__device__ __align__(256) __half g_LMW[(size_t)NPADLM * EE];

// ---------------------------------------------------------------------------
__device__ __forceinline__ uint32_t smem_u32(const void* p) {
    return (uint32_t)__cvta_generic_to_shared(p);
}
__device__ __forceinline__ void cp16(uint32_t dst, const void* src) {
    asm volatile("cp.async.cg.shared.global [%0], [%1], 16;" :: "r"(dst), "l"(src));
}
__device__ __forceinline__ void mma_f16(float* c, const uint32_t* a, const uint32_t* b) {
    asm volatile(
        "mma.sync.aligned.m16n8k16.row.col.f32.f16.f16.f32 "
        "{%0,%1,%2,%3},{%4,%5,%6,%7},{%8,%9},{%0,%1,%2,%3};"
        : "+f"(c[0]), "+f"(c[1]), "+f"(c[2]), "+f"(c[3])
        : "r"(a[0]), "r"(a[1]), "r"(a[2]), "r"(a[3]), "r"(b[0]), "r"(b[1]));
}
__device__ __forceinline__ void ldmx4(uint32_t* r, uint32_t addr) {
    asm volatile("ldmatrix.sync.aligned.m8n8.x4.shared.b16 {%0,%1,%2,%3}, [%4];"
                 : "=r"(r[0]), "=r"(r[1]), "=r"(r[2]), "=r"(r[3]) : "r"(addr));
}
__device__ __forceinline__ void split_h(float v, __half& hi, __half& lo) {
    hi = __float2half(v);
    lo = __float2half(v - __half2float(hi));
}

// ---------------------------------------------------------------------------
// Embedding
// ---------------------------------------------------------------------------
__global__ void embed_k(const int* __restrict__ tok,
                        const float* __restrict__ wte,
                        const float* __restrict__ wpe,
                        float* __restrict__ X)
{
    int row = blockIdx.x;
    int s   = row & (SS - 1);
    int t   = tok[row];
    const float* we = wte + (size_t)t * EE;
    const float* wp = wpe + (size_t)s * EE;
    float* xr = X + (size_t)row * EE;
    for (int e = threadIdx.x; e < EE; e += blockDim.x)
        xr[e] = we[e] + wp[e];
}

// ---------------------------------------------------------------------------
// LayerNorm -> split fp16 hi/lo
// ---------------------------------------------------------------------------
__global__ __launch_bounds__(256) void ln_split_k(const float* __restrict__ X,
                                                  const float* __restrict__ gam,
                                                  const float* __restrict__ bet,
                                                  __half* __restrict__ Oh,
                                                  __half* __restrict__ Ol)
{
    __shared__ float s1[8], s2[8];
    int row = blockIdx.x, tid = threadIdx.x;
    const float* xr = X + (size_t)row * EE;
    float v[3];
    float sum = 0.f, sq = 0.f;
#pragma unroll
    for (int k = 0; k < 3; k++) {
        v[k] = xr[tid + k * 256];
        sum += v[k];
        sq  += v[k] * v[k];
    }
#pragma unroll
    for (int o = 16; o > 0; o >>= 1) {
        sum += __shfl_xor_sync(0xffffffffu, sum, o);
        sq  += __shfl_xor_sync(0xffffffffu, sq,  o);
    }
    if ((tid & 31) == 0) { s1[tid >> 5] = sum; s2[tid >> 5] = sq; }
    __syncthreads();
    sum = 0.f; sq = 0.f;
#pragma unroll
    for (int i = 0; i < 8; i++) { sum += s1[i]; sq += s2[i]; }
    const float inv_n = 1.0f / (float)EE;
    float mu  = sum * inv_n;
    float var = sq * inv_n - mu * mu;
    float rs  = rsqrtf(var + 1e-5f);
#pragma unroll
    for (int k = 0; k < 3; k++) {
        int e = tid + k * 256;
        float y = (v[k] - mu) * rs * gam[e] + bet[e];
        __half hi, lo; split_h(y, hi, lo);
        Oh[(size_t)row * EE + e] = hi;
        Ol[(size_t)row * EE + e] = lo;
    }
}

// ---------------------------------------------------------------------------
// Weight split+transpose: Bg[K,N] fp32 -> Bh,Bl [N,K] fp16 (3-term weights)
// ---------------------------------------------------------------------------
__global__ void splitT3_k(const float* __restrict__ Bg,
                          __half* __restrict__ Bh,
                          __half* __restrict__ Bl, int K, int N)
{
    __shared__ float t[32][33];
    int n0 = blockIdx.x * 32, k0 = blockIdx.y * 32;
    int tx = threadIdx.x, ty = threadIdx.y;
#pragma unroll
    for (int i = 0; i < 4; i++)
        t[ty + 8 * i][tx] = Bg[(size_t)(k0 + ty + 8 * i) * N + n0 + tx];
    __syncthreads();
#pragma unroll
    for (int i = 0; i < 4; i++) {
        int n = n0 + ty + 8 * i;
        int k = k0 + tx;
        __half hi, lo; split_h(t[tx][ty + 8 * i], hi, lo);
        Bh[(size_t)n * K + k] = hi;
        Bl[(size_t)n * K + k] = lo;
    }
}

// Single-fp16 transpose with zero pad (LM head weights)
__global__ void splitT1_k(const float* __restrict__ Bg,
                          __half* __restrict__ Bo, int K, int N)
{
    __shared__ float t[32][33];
    int n0 = blockIdx.x * 32, k0 = blockIdx.y * 32;
    int tx = threadIdx.x, ty = threadIdx.y;
#pragma unroll
    for (int i = 0; i < 4; i++) {
        int n = n0 + tx;
        t[ty + 8 * i][tx] = (n < N) ? Bg[(size_t)(k0 + ty + 8 * i) * N + n] : 0.f;
    }
    __syncthreads();
#pragma unroll
    for (int i = 0; i < 4; i++) {
        int n = n0 + ty + 8 * i;
        Bo[(size_t)n * K + k0 + tx] = __float2half(t[tx][ty + 8 * i]);
    }
}

// ---------------------------------------------------------------------------
// fp16-split GEMM: C[M,N] = A[M,K] @ W[N,K]^T
// NA/NB: split terms per operand. NA=2,NB=2 -> 3 MMAs (hh+hl+lh);
// NA=2,NB=1 -> 2 MMAs; NSTG-stage cp.async pipeline; RS=40 pad.
// ---------------------------------------------------------------------------
#define RS 40
#define KC 32

template<int BM, int BN, int WM, int WN, int NA, int NB, int NSTG,
         bool BIAS, bool GELU, bool RES, bool NGUARD, bool OSPLIT>
__global__ void __launch_bounds__(((BM/WM)*(BN/WN))*32)
hgemm(const __half* __restrict__ Ah, const __half* __restrict__ Al,
      const __half* __restrict__ Bh, const __half* __restrict__ Bl,
      const float* __restrict__ bias, const float* __restrict__ res,
      float* __restrict__ C, __half* __restrict__ Oh, __half* __restrict__ Ol,
      int N, int K)
{
    constexpr int WARPS_M = BM / WM;
    constexpr int NTHR = WARPS_M * (BN / WN) * 32;
    constexpr int MT = WM / 16, NT = WN / 8;
    constexpr int STG = (NA * BM + NB * BN) * RS;       // halfs per stage
    constexpr int OAl = BM * RS;                        // (only if NA==2)
    constexpr int OBh = NA * BM * RS;
    constexpr int OBl = NA * BM * RS + BN * RS;
    constexpr int CH  = (NA * BM + NB * BN) * 4;        // 16B chunks per stage

    extern __shared__ __half sm[];

    const int tid = threadIdx.x, lane = tid & 31, wid = tid >> 5;
    const int wm = (wid % WARPS_M) * WM, wn = (wid / WARPS_M) * WN;
    const int bm = blockIdx.x * BM, bn = blockIdx.y * BN;

    float acc[MT][NT][4];
#pragma unroll
    for (int i = 0; i < MT; i++)
#pragma unroll
        for (int j = 0; j < NT; j++)
#pragma unroll
            for (int t = 0; t < 4; t++) acc[i][j][t] = 0.f;

    const int nIter = K / KC;

    auto load_stage = [&](int it, int s) {
        const int k0 = it * KC;
#pragma unroll
        for (int t = 0; t < CH / NTHR; t++) {
            int c = tid + t * NTHR;
            int ridx = c >> 2, part = c & 3;
            const __half* g; int off;
            if (NA == 2 && ridx < BM)      { g = Ah + (size_t)(bm + ridx) * K; off = ridx * RS; }
            else if (NA == 2 && ridx < 2 * BM)
                { int r = ridx - BM; g = Al + (size_t)(bm + r) * K; off = OAl + r * RS; }
            else if (NA == 1 && ridx < BM) { g = Ah + (size_t)(bm + ridx) * K; off = ridx * RS; }
            else if (NB == 1 || ridx < NA * BM + BN)
                { int r = ridx - NA * BM; g = Bh + (size_t)(bn + r) * K; off = OBh + r * RS; }
            else
                { int r = ridx - NA * BM - BN; g = Bl + (size_t)(bn + r) * K; off = OBl + r * RS; }
            cp16(smem_u32(sm + s * STG + off + part * 8), g + k0 + part * 8);
        }
        asm volatile("cp.async.commit_group;");
    };

    // Prologue: fill NSTG-1 stages
#pragma unroll
    for (int c = 0; c < NSTG - 1; c++) load_stage(c, c);

    const int a_lane = (wm + (lane & 15)) * RS + ((lane >> 4) << 3);
    const int b_lane = (wn + ((lane >> 4) << 3) + (lane & 7)) * RS + (((lane >> 3) & 1) << 3);

    for (int it = 0; it < nIter; it++) {
        const int s = it % NSTG;
        asm volatile("cp.async.wait_group %0;" :: "n"(NSTG - 2));
        __syncthreads();
        if (it + NSTG - 1 < nIter)
            load_stage(it + NSTG - 1, (it + NSTG - 1) % NSTG);

        const __half* stg = sm + s * STG;
#pragma unroll
        for (int kh = 0; kh < 2; kh++) {
            uint32_t ah[MT][4], al[MT][4];
#pragma unroll
            for (int mt = 0; mt < MT; mt++) {
                ldmx4(ah[mt], smem_u32(stg + a_lane + mt * 16 * RS + kh * 16));
                if (NA == 2)
                    ldmx4(al[mt], smem_u32(stg + OAl + a_lane + mt * 16 * RS + kh * 16));
            }
#pragma unroll
            for (int ntb = 0; ntb < NT / 4; ntb++) {
                uint32_t bh[4][2], bl[4][2];
#pragma unroll
                for (int p = 0; p < 2; p++) {
                    const int nt = ntb * 4 + p * 2;
                    uint32_t r4[4];
                    ldmx4(r4, smem_u32(stg + OBh + b_lane + nt * 8 * RS + kh * 16));
                    bh[p*2][0] = r4[0]; bh[p*2][1] = r4[1];
                    bh[p*2+1][0] = r4[2]; bh[p*2+1][1] = r4[3];
                    if (NB == 2) {
                        ldmx4(r4, smem_u32(stg + OBl + b_lane + nt * 8 * RS + kh * 16));
                        bl[p*2][0] = r4[0]; bl[p*2][1] = r4[1];
                        bl[p*2+1][0] = r4[2]; bl[p*2+1][1] = r4[3];
                    }
                }
#pragma unroll
                for (int mt = 0; mt < MT; mt++)
#pragma unroll
                    for (int j = 0; j < 4; j++) {
                        const int nt = ntb * 4 + j;
                        mma_f16(acc[mt][nt], ah[mt], bh[j]);
                        if (NB == 2) mma_f16(acc[mt][nt], ah[mt], bl[j]);
                        if (NA == 2) mma_f16(acc[mt][nt], al[mt], bh[j]);
                    }
            }
        }
        __syncthreads();
    }

    // Epilogue: per mma tile, (r = fr[+8], c = 2*fc[+1])
    const int fr = lane >> 2, fc = lane & 3;
#pragma unroll
    for (int mt = 0; mt < MT; mt++) {
        int row0 = bm + wm + mt * 16 + fr;
#pragma unroll
        for (int nt = 0; nt < NT; nt++) {
            int col = bn + wn + nt * 8 + 2 * fc;
#pragma unroll
            for (int h = 0; h < 2; h++) {
                int rr = row0 + h * 8;
                float v0 = acc[mt][nt][h * 2 + 0];
                float v1 = acc[mt][nt][h * 2 + 1];
                if (BIAS) { v0 += bias[col]; v1 += bias[col + 1]; }
                if (GELU) {
                    v0 = 0.5f * v0 * (1.f + erff(v0 * 0.70710678118654752f));
                    v1 = 0.5f * v1 * (1.f + erff(v1 * 0.70710678118654752f));
                }
                if (RES) {
                    v0 += res[(size_t)rr * N + col];
                    v1 += res[(size_t)rr * N + col + 1];
                }
                if (OSPLIT) {
                    __half h0, l0, h1, l1;
                    split_h(v0, h0, l0);
                    split_h(v1, h1, l1);
                    *(__half2*)(Oh + (size_t)rr * N + col) = __halves2half2(h0, h1);
                    *(__half2*)(Ol + (size_t)rr * N + col) = __halves2half2(l0, l1);
                } else if (!NGUARD) {
                    *(float2*)&C[(size_t)rr * N + col] = make_float2(v0, v1);
                } else {
                    if (col < N)     C[(size_t)rr * N + col]     = v0;
                    if (col + 1 < N) C[(size_t)rr * N + col + 1] = v1;
                }
            }
        }
    }
}

// ---------------------------------------------------------------------------
// Causal attention (online softmax); epilogue writes split fp16 hi/lo.
// ---------------------------------------------------------------------------
__global__ __launch_bounds__(256) void attn_k(const float* __restrict__ QKV,
                                              __half* __restrict__ Oh,
                                              __half* __restrict__ Ol)
{
    const int TQ = 64, TK = 32;
    __shared__ float Qs[TQ][DD + 1];
    __shared__ float Kt[DD][TK];
    __shared__ float Vs[TK][DD];
    __shared__ float Ps[TQ][TK + 1];
    __shared__ float red[TQ][4];

    int tid = threadIdx.x;
    int qt = blockIdx.x, h = blockIdx.y, b = blockIdx.z;
    int r  = tid >> 2;
    int q4 = tid & 3;
    int qi = qt * TQ + r;

    const size_t rstride = 3 * EE;
    const float* qkvb = QKV + (size_t)b * SS * rstride;

    for (int i = tid; i < TQ * DD; i += 256) {
        int rr = i >> 6, d = i & 63;
        Qs[rr][d] = qkvb[(size_t)(qt * TQ + rr) * rstride + h * DD + d];
    }

    float m = -INFINITY, l = 0.f;
    float o[16];
#pragma unroll
    for (int j = 0; j < 16; j++) o[j] = 0.f;
    const float scale = 0.125f;

    int nkt = (qt + 1) * (TQ / TK);
    for (int kt = 0; kt < nkt; kt++) {
        __syncthreads();
        for (int i = tid; i < TK * DD; i += 256) {
            int rr = i >> 6, d = i & 63;
            size_t base = (size_t)(kt * TK + rr) * rstride + h * DD + d;
            Kt[d][rr] = qkvb[EE + base];
            Vs[rr][d] = qkvb[2 * EE + base];
        }
        __syncthreads();

        float sc[8];
#pragma unroll
        for (int j = 0; j < 8; j++) sc[j] = 0.f;
#pragma unroll 8
        for (int d = 0; d < DD; d++) {
            float qv = Qs[r][d];
            float4 k0 = *(const float4*)&Kt[d][q4 * 8];
            float4 k1 = *(const float4*)&Kt[d][q4 * 8 + 4];
            sc[0] = fmaf(qv, k0.x, sc[0]);
            sc[1] = fmaf(qv, k0.y, sc[1]);
            sc[2] = fmaf(qv, k0.z, sc[2]);
            sc[3] = fmaf(qv, k0.w, sc[3]);
            sc[4] = fmaf(qv, k1.x, sc[4]);
            sc[5] = fmaf(qv, k1.y, sc[5]);
            sc[6] = fmaf(qv, k1.z, sc[6]);
            sc[7] = fmaf(qv, k1.w, sc[7]);
        }
        float lmax = -INFINITY;
#pragma unroll
        for (int j = 0; j < 8; j++) {
            int kg = kt * TK + q4 * 8 + j;
            sc[j] = (kg <= qi) ? sc[j] * scale : -1e30f;
            lmax = fmaxf(lmax, sc[j]);
        }
        red[r][q4] = lmax;
        __syncthreads();
        float mnew = fmaxf(fmaxf(fmaxf(red[r][0], red[r][1]),
                                 fmaxf(red[r][2], red[r][3])), m);
        __syncthreads();

        float lsum = 0.f;
#pragma unroll
        for (int j = 0; j < 8; j++) {
            float p = __expf(sc[j] - mnew);
            Ps[r][q4 * 8 + j] = p;
            lsum += p;
        }
        red[r][q4] = lsum;
        __syncthreads();
        float tsum = red[r][0] + red[r][1] + red[r][2] + red[r][3];
        float fac = __expf(m - mnew);
        l = l * fac + tsum;
        m = mnew;
#pragma unroll
        for (int j = 0; j < 16; j++) o[j] *= fac;

#pragma unroll 4
        for (int c = 0; c < TK; c++) {
            float p = Ps[r][c];
            float4 v0 = *(const float4*)&Vs[c][q4 * 16 + 0];
            float4 v1 = *(const float4*)&Vs[c][q4 * 16 + 4];
            float4 v2 = *(const float4*)&Vs[c][q4 * 16 + 8];
            float4 v3 = *(const float4*)&Vs[c][q4 * 16 + 12];
            o[0]  = fmaf(p, v0.x, o[0]);  o[1]  = fmaf(p, v0.y, o[1]);
            o[2]  = fmaf(p, v0.z, o[2]);  o[3]  = fmaf(p, v0.w, o[3]);
            o[4]  = fmaf(p, v1.x, o[4]);  o[5]  = fmaf(p, v1.y, o[5]);
            o[6]  = fmaf(p, v1.z, o[6]);  o[7]  = fmaf(p, v1.w, o[7]);
            o[8]  = fmaf(p, v2.x, o[8]);  o[9]  = fmaf(p, v2.y, o[9]);
            o[10] = fmaf(p, v2.z, o[10]); o[11] = fmaf(p, v2.w, o[11]);
            o[12] = fmaf(p, v3.x, o[12]); o[13] = fmaf(p, v3.y, o[13]);
            o[14] = fmaf(p, v3.z, o[14]); o[15] = fmaf(p, v3.w, o[15]);
        }
    }

    float inv = 1.f / l;
    size_t obase = ((size_t)b * SS + qi) * EE + h * DD + q4 * 16;
#pragma unroll
    for (int j = 0; j < 16; j++) {
        __half hi, lo;
        split_h(o[j] * inv, hi, lo);
        Oh[obase + j] = hi;
        Ol[obase + j] = lo;
    }
}

// ---------------------------------------------------------------------------
// Host launcher
// ---------------------------------------------------------------------------
extern "C" void kernel_launch(void* const* d_in, const int* in_sizes, int n_in,
                              void* d_out, int out_size)
{
    const int*   tok    = (const int*)  d_in[0];
    const float* wte    = (const float*)d_in[1];
    const float* wpe    = (const float*)d_in[2];
    const float* ln1_g  = (const float*)d_in[3];
    const float* ln1_b  = (const float*)d_in[4];
    const float* attn_w = (const float*)d_in[5];
    const float* attn_b = (const float*)d_in[6];
    const float* proj_w = (const float*)d_in[7];
    const float* proj_b = (const float*)d_in[8];
    const float* ln2_g  = (const float*)d_in[9];
    const float* ln2_b  = (const float*)d_in[10];
    const float* fc_w   = (const float*)d_in[11];
    const float* fc_b   = (const float*)d_in[12];
    const float* fc2_w  = (const float*)d_in[13];
    const float* fc2_b  = (const float*)d_in[14];
    const float* lnf_g  = (const float*)d_in[15];
    const float* lnf_b  = (const float*)d_in[16];
    const float* lm_w   = (const float*)d_in[17];
    float* out = (float*)d_out;

    float *X, *QKV;
    __half *Ah, *Al, *Fh, *Fl, *Wh, *Wl, *LMW;
    cudaGetSymbolAddress((void**)&X,   g_X);
    cudaGetSymbolAddress((void**)&QKV, g_QKV);
    cudaGetSymbolAddress((void**)&Ah,  g_Ah);
    cudaGetSymbolAddress((void**)&Al,  g_Al);
    cudaGetSymbolAddress((void**)&Fh,  g_Fh);
    cudaGetSymbolAddress((void**)&Fl,  g_Fl);
    cudaGetSymbolAddress((void**)&Wh,  g_Wh);
    cudaGetSymbolAddress((void**)&Wl,  g_Wl);
    cudaGetSymbolAddress((void**)&LMW, g_LMW);

    // GEMM configs
    //  ALL layer GEMMs: 128x128 tile, 512 thr (16 warps, 32x32 warp tiles),
    //  3-term, 2-stage. LM head: 128x256, 512 thr, 2-term (A split, B fp16).
    auto lay_f  = hgemm<128,128,32,32,2,2,2, true,false,false,false,false>;
    auto layr_f = hgemm<128,128,32,32,2,2,2, true,false,true, false,false>;
    auto fc1_f  = hgemm<128,128,32,32,2,2,2, true,true, false,false,true>;
    auto lm_f   = hgemm<128,256,32,64,2,1,2, false,false,false,true,false>;

    const int SM_LAY = 2 * (2*128 + 2*128) * RS * 2;    //  81920 B
    const int SM_LM  = 2 * (2*128 + 1*256) * RS * 2;    //  81920 B
    cudaFuncSetAttribute(lay_f,  cudaFuncAttributeMaxDynamicSharedMemorySize, SM_LAY);
    cudaFuncSetAttribute(layr_f, cudaFuncAttributeMaxDynamicSharedMemorySize, SM_LAY);
    cudaFuncSetAttribute(fc1_f,  cudaFuncAttributeMaxDynamicSharedMemorySize, SM_LAY);
    cudaFuncSetAttribute(lm_f,   cudaFuncAttributeMaxDynamicSharedMemorySize, SM_LM);

    embed_k<<<MM, 256>>>(tok, wte, wpe, X);

    for (int i = 0; i < LL; i++) {
        // LN1 -> split
        ln_split_k<<<MM, 256>>>(X, ln1_g + i * EE, ln1_b + i * EE, Ah, Al);
        // QKV = A @ attn_w + b    [2048 x 2304]
        splitT3_k<<<dim3(3 * EE / 32, EE / 32), dim3(32, 8)>>>(
            attn_w + (size_t)i * EE * 3 * EE, Wh, Wl, EE, 3 * EE);
        lay_f<<<dim3(MM / 128, 3 * EE / 128), 512, SM_LAY>>>(
            Ah, Al, Wh, Wl, attn_b + (size_t)i * 3 * EE, nullptr,
            QKV, nullptr, nullptr, 3 * EE, EE);
        // attention -> split
        attn_k<<<dim3(SS / 64, HH, BB), 256>>>(QKV, Ah, Al);
        // X += A @ proj_w + b     [2048 x 768]
        splitT3_k<<<dim3(EE / 32, EE / 32), dim3(32, 8)>>>(
            proj_w + (size_t)i * EE * EE, Wh, Wl, EE, EE);
        layr_f<<<dim3(MM / 128, EE / 128), 512, SM_LAY>>>(
            Ah, Al, Wh, Wl, proj_b + (size_t)i * EE, X,
            X, nullptr, nullptr, EE, EE);
        // LN2 -> split
        ln_split_k<<<MM, 256>>>(X, ln2_g + i * EE, ln2_b + i * EE, Ah, Al);
        // F = gelu(A @ fc_w + b) -> split   [2048 x 3072]
        splitT3_k<<<dim3(4 * EE / 32, EE / 32), dim3(32, 8)>>>(
            fc_w + (size_t)i * EE * 4 * EE, Wh, Wl, EE, 4 * EE);
        fc1_f<<<dim3(MM / 128, 4 * EE / 128), 512, SM_LAY>>>(
            Ah, Al, Wh, Wl, fc_b + (size_t)i * 4 * EE, nullptr,
            nullptr, Fh, Fl, 4 * EE, EE);
        // X += F @ fc2_w + b      [2048 x 768], K=3072
        splitT3_k<<<dim3(EE / 32, 4 * EE / 32), dim3(32, 8)>>>(
            fc2_w + (size_t)i * 4 * EE * EE, Wh, Wl, 4 * EE, EE);
        layr_f<<<dim3(MM / 128, EE / 128), 512, SM_LAY>>>(
            Fh, Fl, Wh, Wl, fc2_b + (size_t)i * EE, X,
            X, nullptr, nullptr, EE, 4 * EE);
    }

    // final LN -> split, LM head (2-term: A split, B fp16; guarded stores)
    ln_split_k<<<MM, 256>>>(X, lnf_g, lnf_b, Ah, Al);
    splitT1_k<<<dim3(NPADLM / 32, EE / 32), dim3(32, 8)>>>(lm_w, LMW, EE, VV);
    lm_f<<<dim3(MM / 128, NPADLM / 256), 512, SM_LM>>>(
        Ah, Al, LMW, nullptr, nullptr, nullptr,
        out, nullptr, nullptr, VV, EE);
}